// round 3
// baseline (speedup 1.0000x reference)
#include <cuda_runtime.h>
#include <math.h>

// Problem dims (fixed by the dataset)
#define Bn 4
#define Cc 1024
#define Tt 4096
#define Dd 256
#define Kc 8192
#define Mm (Bn*Tt)   // 16384

// Output layout: (out [B,C,T], indices [B,T] as float, z_e [B,D,T])
#define OUT_OUT 0
#define OUT_IDX (Bn*Cc*Tt)            // 16777216
#define OUT_ZE  (OUT_IDX + Bn*Tt)     // 16793600

#define NEG_INF (-3.402823466e38f)

// Scratch (device globals; no runtime allocation)
__device__ float g_Win[Dd*Cc];     // 1 MB
__device__ float g_Wout[Cc*Dd];    // 1 MB
__device__ float g_cbn[Kc*Dd];     // 8 MB  (normalized codebook)
__device__ float g_zeT[(size_t)Mm*Dd];  // 16 MB (z_e transposed: [b*T+t][d])
__device__ float g_zq[(size_t)Bn*Dd*Tt]; // 16 MB ([b][d][t])
__device__ int   g_idx[Mm];

// ---------------------------------------------------------------------------
// Row-wise L2 normalize (+optional gain): mode 0 -> W_in, 1 -> W_out, 2 -> cb_n
// ---------------------------------------------------------------------------
__global__ __launch_bounds__(256) void rownorm_kernel(
    const float* __restrict__ v, const float* __restrict__ g, int mode, int cols)
{
    int r = blockIdx.x;
    const float* row = v + (size_t)r * cols;
    float s = 0.f;
    for (int c = threadIdx.x; c < cols; c += 256) { float x = row[c]; s += x * x; }
    __shared__ float red[32];
    #pragma unroll
    for (int o = 16; o; o >>= 1) s += __shfl_down_sync(0xffffffffu, s, o);
    int lane = threadIdx.x & 31, w = threadIdx.x >> 5;
    if (lane == 0) red[w] = s;
    __syncthreads();
    if (w == 0) {
        s = (lane < 8) ? red[lane] : 0.f;
        #pragma unroll
        for (int o = 4; o; o >>= 1) s += __shfl_down_sync(0xffffffffu, s, o);
        if (lane == 0) red[0] = s;
    }
    __syncthreads();
    float nrm = sqrtf(red[0]);
    float scale;
    if (mode == 2) scale = 1.f / fmaxf(nrm, 1e-12f);
    else           scale = g[r] / nrm;
    float* out = (mode == 0) ? g_Win : (mode == 1) ? g_Wout : g_cbn;
    float* orow = out + (size_t)r * cols;
    for (int c = threadIdx.x; c < cols; c += 256) orow[c] = row[c] * scale;
}

// ---------------------------------------------------------------------------
// GEMM-in: z_e[b,d,t] = sum_c W_in[d,c] * z[b,c,t] + in_b[d]
// Writes z_e to d_out (OUT_ZE region, [B,D,T]) and z_eT scratch ([b*T+t][d]).
// 64x64 tile, 256 threads, 4x4 micro-tile, K=1024 in BK=16 steps.
// ---------------------------------------------------------------------------
__global__ __launch_bounds__(256) void gemm_in_kernel(
    const float* __restrict__ z, const float* __restrict__ in_b,
    float* __restrict__ out)
{
    const int b  = blockIdx.z;
    const int d0 = blockIdx.y * 64;
    const int t0 = blockIdx.x * 64;
    __shared__ float As[16][64];   // [k][d]
    __shared__ float Bs[16][64];   // [k][t]
    __shared__ float Cs[64][65];   // [t][d] transpose buffer

    float acc[4][4] = {};
    const int tid = threadIdx.x;
    const int tx = tid & 15, ty = tid >> 4;
    const float* Zb = z + (size_t)b * Cc * Tt;

    for (int k0 = 0; k0 < Cc; k0 += 16) {
        {
            int d  = tid >> 2;
            int kq = (tid & 3) << 2;
            float4 va = *(const float4*)(g_Win + (size_t)(d0 + d) * Cc + k0 + kq);
            As[kq + 0][d] = va.x; As[kq + 1][d] = va.y;
            As[kq + 2][d] = va.z; As[kq + 3][d] = va.w;
            int kk = tid >> 4;
            int tq = (tid & 15) << 2;
            float4 vb = *(const float4*)(Zb + (size_t)(k0 + kk) * Tt + t0 + tq);
            *(float4*)&Bs[kk][tq] = vb;
        }
        __syncthreads();
        #pragma unroll
        for (int kk = 0; kk < 16; kk++) {
            float a[4], bb[4];
            #pragma unroll
            for (int i = 0; i < 4; i++) a[i] = As[kk][(ty << 2) + i];
            #pragma unroll
            for (int j = 0; j < 4; j++) bb[j] = Bs[kk][(tx << 2) + j];
            #pragma unroll
            for (int i = 0; i < 4; i++)
                #pragma unroll
                for (int j = 0; j < 4; j++)
                    acc[i][j] = fmaf(a[i], bb[j], acc[i][j]);
        }
        __syncthreads();
    }
    // epilogue: +bias, write z_e ([B,D,T]) and stage transpose
    #pragma unroll
    for (int i = 0; i < 4; i++) {
        int dl = (ty << 2) + i;
        int d  = d0 + dl;
        float bias = in_b[d];
        float4 v;
        v.x = acc[i][0] + bias; v.y = acc[i][1] + bias;
        v.z = acc[i][2] + bias; v.w = acc[i][3] + bias;
        *(float4*)(out + OUT_ZE + ((size_t)(b * Dd + d)) * Tt + t0 + (tx << 2)) = v;
        Cs[(tx << 2) + 0][dl] = v.x; Cs[(tx << 2) + 1][dl] = v.y;
        Cs[(tx << 2) + 2][dl] = v.z; Cs[(tx << 2) + 3][dl] = v.w;
    }
    __syncthreads();
    // z_eT write: coalesced over d
    #pragma unroll
    for (int r = 0; r < 16; r++) {
        int tl = (tid >> 6) + (r << 2);
        int dl = tid & 63;
        g_zeT[((size_t)(b * Tt + t0 + tl)) * Dd + d0 + dl] = Cs[tl][dl];
    }
}

// ---------------------------------------------------------------------------
// Scoring + argmax: for each row m (=b*T+t), idx = argmax_k <z_eT[m], cb_n[k]>
// Block: 64 rows, loops N=8192 in 128-wide tiles. E-tile (64x256) resident in
// smem. 256 threads, 4x8 micro-tile. First-index tie-break to match argmax.
// Dynamic smem: Es[256][68] + Cbs[16][132] = 78080 B.
// ---------------------------------------------------------------------------
#define ES_STRIDE 68
#define CB_STRIDE 132
#define ARGMAX_SMEM ((256*ES_STRIDE + 16*CB_STRIDE) * 4)

__global__ __launch_bounds__(256) void argmax_kernel(float* __restrict__ out)
{
    extern __shared__ float sm[];
    float* Es  = sm;                    // [256][68]  -> Es[k*68 + m]
    float* Cbs = sm + 256 * ES_STRIDE;  // [16][132]  -> Cbs[k*132 + n]

    const int m0  = blockIdx.x * 64;
    const int tid = threadIdx.x;
    const int tx = tid & 15, ty = tid >> 4;

    // load e-tile (transposed into [k][m])
    #pragma unroll
    for (int r = 0; r < 16; r++) {
        int m  = (tid >> 6) + (r << 2);
        int k4 = (tid & 63) << 2;
        float4 v = *(const float4*)(g_zeT + (size_t)(m0 + m) * Dd + k4);
        Es[(k4 + 0) * ES_STRIDE + m] = v.x;
        Es[(k4 + 1) * ES_STRIDE + m] = v.y;
        Es[(k4 + 2) * ES_STRIDE + m] = v.z;
        Es[(k4 + 3) * ES_STRIDE + m] = v.w;
    }
    __syncthreads();

    float best[4]; int bidx[4];
    #pragma unroll
    for (int i = 0; i < 4; i++) { best[i] = NEG_INF; bidx[i] = 0; }

    for (int n0 = 0; n0 < Kc; n0 += 128) {
        float acc[4][8] = {};
        for (int k0 = 0; k0 < Dd; k0 += 16) {
            {
                int n_l = tid >> 1;
                int k_l = (tid & 1) << 3;
                const float* src = g_cbn + (size_t)(n0 + n_l) * Dd + k0 + k_l;
                float4 v0 = *(const float4*)(src);
                float4 v1 = *(const float4*)(src + 4);
                float* dst = Cbs + n_l;
                dst[(k_l + 0) * CB_STRIDE] = v0.x; dst[(k_l + 1) * CB_STRIDE] = v0.y;
                dst[(k_l + 2) * CB_STRIDE] = v0.z; dst[(k_l + 3) * CB_STRIDE] = v0.w;
                dst[(k_l + 4) * CB_STRIDE] = v1.x; dst[(k_l + 5) * CB_STRIDE] = v1.y;
                dst[(k_l + 6) * CB_STRIDE] = v1.z; dst[(k_l + 7) * CB_STRIDE] = v1.w;
            }
            __syncthreads();
            #pragma unroll
            for (int kk = 0; kk < 16; kk++) {
                float4 a  = *(const float4*)&Es[(k0 + kk) * ES_STRIDE + (ty << 2)];
                float4 b0 = *(const float4*)&Cbs[kk * CB_STRIDE + (tx << 3)];
                float4 b1 = *(const float4*)&Cbs[kk * CB_STRIDE + (tx << 3) + 4];
                float av[4] = {a.x, a.y, a.z, a.w};
                float bv[8] = {b0.x, b0.y, b0.z, b0.w, b1.x, b1.y, b1.z, b1.w};
                #pragma unroll
                for (int i = 0; i < 4; i++)
                    #pragma unroll
                    for (int j = 0; j < 8; j++)
                        acc[i][j] = fmaf(av[i], bv[j], acc[i][j]);
            }
            __syncthreads();
        }
        // running argmax (ascending n => strict > keeps earliest index)
        #pragma unroll
        for (int i = 0; i < 4; i++)
            #pragma unroll
            for (int j = 0; j < 8; j++) {
                float v = acc[i][j];
                if (v > best[i]) { best[i] = v; bidx[i] = n0 + (tx << 3) + j; }
            }
    }
    __syncthreads();
    // cross-tx reduction (reuse smem)
    float* sB = sm;                 // [64][16]
    int*   sI = (int*)(sm + 64 * 16);
    #pragma unroll
    for (int i = 0; i < 4; i++) {
        sB[((ty << 2) + i) * 16 + tx] = best[i];
        sI[((ty << 2) + i) * 16 + tx] = bidx[i];
    }
    __syncthreads();
    if (tid < 64) {
        float bv = NEG_INF; int bi = 0x7fffffff;
        #pragma unroll
        for (int c = 0; c < 16; c++) {
            float v = sB[tid * 16 + c]; int n = sI[tid * 16 + c];
            if (v > bv || (v == bv && n < bi)) { bv = v; bi = n; }
        }
        g_idx[m0 + tid] = bi;
        out[OUT_IDX + m0 + tid] = (float)bi;
    }
    __syncthreads();
}

// ---------------------------------------------------------------------------
// Gather z_q[b,d,t] = codebook[idx[b,t]][d]  (un-normalized codebook)
// Block: 32 t's; coalesced codebook reads, smem transpose, float4 writes.
// ---------------------------------------------------------------------------
__global__ __launch_bounds__(256) void gather_kernel(const float* __restrict__ cb)
{
    __shared__ float Ds[32][260];
    const int m0  = blockIdx.x * 32;    // b*T + t0
    const int tid = threadIdx.x;
    {
        int t_l = tid >> 3;
        int d0  = (tid & 7) << 5;
        int code = g_idx[m0 + t_l];
        const float* crow = cb + (size_t)code * Dd;
        #pragma unroll
        for (int q = 0; q < 8; q++) {
            float4 v = *(const float4*)(crow + d0 + (q << 2));
            *(float4*)&Ds[t_l][d0 + (q << 2)] = v;
        }
    }
    __syncthreads();
    {
        int d  = tid;
        int b  = m0 >> 12;
        int t0 = m0 & (Tt - 1);
        float* wr = g_zq + ((size_t)(b * Dd + d)) * Tt + t0;
        #pragma unroll
        for (int q = 0; q < 8; q++) {
            float4 v;
            v.x = Ds[(q << 2) + 0][d]; v.y = Ds[(q << 2) + 1][d];
            v.z = Ds[(q << 2) + 2][d]; v.w = Ds[(q << 2) + 3][d];
            *(float4*)(wr + (q << 2)) = v;
        }
    }
}

// ---------------------------------------------------------------------------
// GEMM-out: out[b,c,t] = sum_d W_out[c,d] * z_q[b,d,t] + out_b[c]
// ---------------------------------------------------------------------------
__global__ __launch_bounds__(256) void gemm_out_kernel(
    const float* __restrict__ out_b, float* __restrict__ out)
{
    const int b  = blockIdx.z;
    const int c0 = blockIdx.y * 64;
    const int t0 = blockIdx.x * 64;
    __shared__ float As[16][64];   // [k][c]
    __shared__ float Bs[16][64];   // [k][t]

    float acc[4][4] = {};
    const int tid = threadIdx.x;
    const int tx = tid & 15, ty = tid >> 4;
    const float* Zb = g_zq + (size_t)b * Dd * Tt;

    for (int k0 = 0; k0 < Dd; k0 += 16) {
        {
            int c  = tid >> 2;
            int kq = (tid & 3) << 2;
            float4 va = *(const float4*)(g_Wout + (size_t)(c0 + c) * Dd + k0 + kq);
            As[kq + 0][c] = va.x; As[kq + 1][c] = va.y;
            As[kq + 2][c] = va.z; As[kq + 3][c] = va.w;
            int kk = tid >> 4;
            int tq = (tid & 15) << 2;
            float4 vb = *(const float4*)(Zb + (size_t)(k0 + kk) * Tt + t0 + tq);
            *(float4*)&Bs[kk][tq] = vb;
        }
        __syncthreads();
        #pragma unroll
        for (int kk = 0; kk < 16; kk++) {
            float a[4], bb[4];
            #pragma unroll
            for (int i = 0; i < 4; i++) a[i] = As[kk][(ty << 2) + i];
            #pragma unroll
            for (int j = 0; j < 4; j++) bb[j] = Bs[kk][(tx << 2) + j];
            #pragma unroll
            for (int i = 0; i < 4; i++)
                #pragma unroll
                for (int j = 0; j < 4; j++)
                    acc[i][j] = fmaf(a[i], bb[j], acc[i][j]);
        }
        __syncthreads();
    }
    #pragma unroll
    for (int i = 0; i < 4; i++) {
        int c = c0 + (ty << 2) + i;
        float bias = out_b[c];
        float4 v;
        v.x = acc[i][0] + bias; v.y = acc[i][1] + bias;
        v.z = acc[i][2] + bias; v.w = acc[i][3] + bias;
        *(float4*)(out + OUT_OUT + ((size_t)(b * Cc + c)) * Tt + t0 + (tx << 2)) = v;
    }
}

// ---------------------------------------------------------------------------
extern "C" void kernel_launch(void* const* d_in, const int* in_sizes, int n_in,
                              void* d_out, int out_size)
{
    const float* z     = (const float*)d_in[0];
    const float* in_v  = (const float*)d_in[1];
    const float* in_g  = (const float*)d_in[2];
    const float* in_b  = (const float*)d_in[3];
    const float* out_v = (const float*)d_in[4];
    const float* out_g = (const float*)d_in[5];
    const float* out_b = (const float*)d_in[6];
    const float* cb    = (const float*)d_in[7];
    float* out = (float*)d_out;

    cudaFuncSetAttribute(argmax_kernel,
                         cudaFuncAttributeMaxDynamicSharedMemorySize, ARGMAX_SMEM);

    // weight norms + codebook normalize
    rownorm_kernel<<<Dd,   256>>>(in_v,  in_g,  0, Cc);
    rownorm_kernel<<<Cc,   256>>>(out_v, out_g, 1, Dd);
    rownorm_kernel<<<Kc,   256>>>(cb,    nullptr, 2, Dd);

    // z_e = W_in @ z + b  (also emits z_eT)
    {
        dim3 grid(Tt / 64, Dd / 64, Bn);
        gemm_in_kernel<<<grid, 256>>>(z, in_b, out);
    }

    // indices = argmax_k <z_e, cb_n[k]>
    argmax_kernel<<<Mm / 64, 256, ARGMAX_SMEM>>>(out);

    // z_q gather
    gather_kernel<<<Mm / 32, 256>>>(cb);

    // out = W_out @ z_q + b
    {
        dim3 grid(Tt / 64, Cc / 64, Bn);
        gemm_out_kernel<<<grid, 256>>>(out_b, out);
    }
}

// round 6
// speedup vs baseline: 1.6720x; 1.6720x over previous
#include <cuda_runtime.h>
#include <math.h>
#include <stdint.h>

// Problem dims (fixed by the dataset)
#define Bn 4
#define Cc 1024
#define Tt 4096
#define Dd 256
#define Kc 8192
#define Mm (Bn*Tt)   // 16384

// Output layout: (out [B,C,T], indices [B,T] as float, z_e [B,D,T])
#define OUT_OUT 0
#define OUT_IDX (Bn*Cc*Tt)            // 16777216
#define OUT_ZE  (OUT_IDX + Bn*Tt)     // 16793600

#define NEG_INF (-3.402823466e38f)

// Scratch (device globals; no runtime allocation)
__device__ float g_Win[Dd*Cc];                 // 1 MB
__device__ float g_Wout[Cc*Dd];                // 1 MB
__device__ float g_cbn_hi[(size_t)Kc*Dd];      // 8 MB  tf32-hi of normalized codebook
__device__ float g_cbn_lo[(size_t)Kc*Dd];      // 8 MB  tf32-lo
__device__ float g_zeT_hi[(size_t)Mm*Dd];      // 16 MB tf32-hi of z_e^T  [m][d]
__device__ float g_zeT_lo[(size_t)Mm*Dd];      // 16 MB tf32-lo
__device__ float g_zq[(size_t)Bn*Dd*Tt];       // 16 MB ([b][d][t])
__device__ int   g_idx[Mm];

__device__ __forceinline__ float to_tf32(float a) {
    uint32_t u;
    asm("cvt.rna.tf32.f32 %0, %1;" : "=r"(u) : "f"(a));
    return __uint_as_float(u);
}

// Warp-level tf32 MMA: D(16x8) += A(16x8) * B(8x8), fp32 accumulate.
__device__ __forceinline__ void mma_tf32(float c[4], const uint32_t a[4],
                                         const uint32_t b[2]) {
    asm volatile(
        "mma.sync.aligned.m16n8k8.row.col.f32.tf32.tf32.f32 "
        "{%0,%1,%2,%3}, {%4,%5,%6,%7}, {%8,%9}, {%0,%1,%2,%3};"
        : "+f"(c[0]), "+f"(c[1]), "+f"(c[2]), "+f"(c[3])
        : "r"(a[0]), "r"(a[1]), "r"(a[2]), "r"(a[3]),
          "r"(b[0]), "r"(b[1]));
}

// ---------------------------------------------------------------------------
// Row-wise L2 normalize: mode 0 -> g_Win, 1 -> g_Wout, 2 -> cbn tf32 splits
// ---------------------------------------------------------------------------
__global__ __launch_bounds__(256) void rownorm_kernel(
    const float* __restrict__ v, const float* __restrict__ g, int mode, int cols)
{
    int r = blockIdx.x;
    const float* row = v + (size_t)r * cols;
    float s = 0.f;
    for (int c = threadIdx.x; c < cols; c += 256) { float x = row[c]; s += x * x; }
    __shared__ float red[32];
    #pragma unroll
    for (int o = 16; o; o >>= 1) s += __shfl_down_sync(0xffffffffu, s, o);
    int lane = threadIdx.x & 31, w = threadIdx.x >> 5;
    if (lane == 0) red[w] = s;
    __syncthreads();
    if (w == 0) {
        s = (lane < 8) ? red[lane] : 0.f;
        #pragma unroll
        for (int o = 4; o; o >>= 1) s += __shfl_down_sync(0xffffffffu, s, o);
        if (lane == 0) red[0] = s;
    }
    __syncthreads();
    float nrm = sqrtf(red[0]);
    if (mode == 2) {
        float scale = 1.f / fmaxf(nrm, 1e-12f);
        for (int c = threadIdx.x; c < cols; c += 256) {
            float x = row[c] * scale;
            float hi = to_tf32(x);
            g_cbn_hi[(size_t)r * cols + c] = hi;
            g_cbn_lo[(size_t)r * cols + c] = to_tf32(x - hi);
        }
    } else {
        float scale = g[r] / nrm;
        float* orow = ((mode == 0) ? g_Win : g_Wout) + (size_t)r * cols;
        for (int c = threadIdx.x; c < cols; c += 256) orow[c] = row[c] * scale;
    }
}

// ---------------------------------------------------------------------------
// GEMM-in: z_e[b,d,t] = sum_c W_in[d,c] * z[b,c,t] + in_b[d]
// Writes z_e to d_out (OUT_ZE) and tf32 hi/lo splits of z_e^T.
// ---------------------------------------------------------------------------
__global__ __launch_bounds__(256) void gemm_in_kernel(
    const float* __restrict__ z, const float* __restrict__ in_b,
    float* __restrict__ out)
{
    const int b  = blockIdx.z;
    const int d0 = blockIdx.y * 64;
    const int t0 = blockIdx.x * 64;
    __shared__ float As[16][64];
    __shared__ float Bs[16][64];
    __shared__ float Cs[64][65];

    float acc[4][4] = {};
    const int tid = threadIdx.x;
    const int tx = tid & 15, ty = tid >> 4;
    const float* Zb = z + (size_t)b * Cc * Tt;

    for (int k0 = 0; k0 < Cc; k0 += 16) {
        {
            int d  = tid >> 2;
            int kq = (tid & 3) << 2;
            float4 va = *(const float4*)(g_Win + (size_t)(d0 + d) * Cc + k0 + kq);
            As[kq + 0][d] = va.x; As[kq + 1][d] = va.y;
            As[kq + 2][d] = va.z; As[kq + 3][d] = va.w;
            int kk = tid >> 4;
            int tq = (tid & 15) << 2;
            float4 vb = *(const float4*)(Zb + (size_t)(k0 + kk) * Tt + t0 + tq);
            *(float4*)&Bs[kk][tq] = vb;
        }
        __syncthreads();
        #pragma unroll
        for (int kk = 0; kk < 16; kk++) {
            float a[4], bb[4];
            #pragma unroll
            for (int i = 0; i < 4; i++) a[i] = As[kk][(ty << 2) + i];
            #pragma unroll
            for (int j = 0; j < 4; j++) bb[j] = Bs[kk][(tx << 2) + j];
            #pragma unroll
            for (int i = 0; i < 4; i++)
                #pragma unroll
                for (int j = 0; j < 4; j++)
                    acc[i][j] = fmaf(a[i], bb[j], acc[i][j]);
        }
        __syncthreads();
    }
    #pragma unroll
    for (int i = 0; i < 4; i++) {
        int dl = (ty << 2) + i;
        int d  = d0 + dl;
        float bias = in_b[d];
        float4 v;
        v.x = acc[i][0] + bias; v.y = acc[i][1] + bias;
        v.z = acc[i][2] + bias; v.w = acc[i][3] + bias;
        *(float4*)(out + OUT_ZE + ((size_t)(b * Dd + d)) * Tt + t0 + (tx << 2)) = v;
        Cs[(tx << 2) + 0][dl] = v.x; Cs[(tx << 2) + 1][dl] = v.y;
        Cs[(tx << 2) + 2][dl] = v.z; Cs[(tx << 2) + 3][dl] = v.w;
    }
    __syncthreads();
    #pragma unroll
    for (int r = 0; r < 16; r++) {
        int tl = (tid >> 6) + (r << 2);
        int dl = tid & 63;
        float v  = Cs[tl][dl];
        float hi = to_tf32(v);
        size_t o = ((size_t)(b * Tt + t0 + tl)) * Dd + d0 + dl;
        g_zeT_hi[o] = hi;
        g_zeT_lo[o] = to_tf32(v - hi);
    }
}

// ---------------------------------------------------------------------------
// Scoring + argmax via warp-level mma.sync tf32, 3-pass split (fp32-accurate).
// CTA: 64 rows, 256 thr = 8 warps (4 m-warps x 2 n-warps), warp tile m16 x n64.
// N in 128-wide tiles; K=256 in 32-wide smem chunks, [m][36]/[n][36] padding
// (conflict-free fragment LDS). Per-tile register argmax -> quad shuffle
// reduce (min-index ties) -> cross-n-warp smem merge.
// ---------------------------------------------------------------------------
#define AK 36
#define ARG_SMEM ((64*AK*2 + 128*AK*2) * 4)   // 55296 B

__global__ __launch_bounds__(256) void argmax_mma_kernel(float* __restrict__ out)
{
    extern __shared__ float smm[];
    float* Ah = smm;                 // [64][36]
    float* Al = smm + 64 * AK;
    float* Bh = smm + 128 * AK;      // [128][36]
    float* Bl = smm + 128 * AK + 128 * AK;

    const int tid  = threadIdx.x;
    const int wid  = tid >> 5, lane = tid & 31;
    const int q    = lane & 3, r = lane >> 2;
    const int mwarp = wid >> 1, nwarp = wid & 1;
    const int m0   = blockIdx.x * 64;
    const int arow0 = (mwarp << 4) + r;

    float acc[8][4] = {};
    float best0 = NEG_INF, best1 = NEG_INF;
    int   bi0 = 0, bi1 = 0;

    for (int tile = 0; tile < Kc / 128; tile++) {
        const int n0 = tile << 7;
        for (int kc = 0; kc < 8; kc++) {
            const int k0 = kc << 5;
            __syncthreads();
            // A chunk: 64 rows x 32 k (hi+lo), coalesced 128B per 4 rows
            {
                int f4 = (lane & 7) << 2;
                #pragma unroll
                for (int p = 0; p < 2; p++) {
                    int row = (p << 5) + (wid << 2) + (lane >> 3);
                    size_t src = (size_t)(m0 + row) * Dd + k0 + f4;
                    *(float4*)&Ah[row * AK + f4] = *(const float4*)(g_zeT_hi + src);
                    *(float4*)&Al[row * AK + f4] = *(const float4*)(g_zeT_lo + src);
                }
                #pragma unroll
                for (int p = 0; p < 4; p++) {
                    int row = (p << 5) + (wid << 2) + (lane >> 3);
                    size_t src = (size_t)(n0 + row) * Dd + k0 + f4;
                    *(float4*)&Bh[row * AK + f4] = *(const float4*)(g_cbn_hi + src);
                    *(float4*)&Bl[row * AK + f4] = *(const float4*)(g_cbn_lo + src);
                }
            }
            __syncthreads();
            #pragma unroll
            for (int k8 = 0; k8 < 4; k8++) {
                const int kk = (k8 << 3) + q;
                uint32_t ah[4], al[4];
                ah[0] = __float_as_uint(Ah[arow0 * AK + kk]);
                ah[1] = __float_as_uint(Ah[(arow0 + 8) * AK + kk]);
                ah[2] = __float_as_uint(Ah[arow0 * AK + kk + 4]);
                ah[3] = __float_as_uint(Ah[(arow0 + 8) * AK + kk + 4]);
                al[0] = __float_as_uint(Al[arow0 * AK + kk]);
                al[1] = __float_as_uint(Al[(arow0 + 8) * AK + kk]);
                al[2] = __float_as_uint(Al[arow0 * AK + kk + 4]);
                al[3] = __float_as_uint(Al[(arow0 + 8) * AK + kk + 4]);
                #pragma unroll
                for (int s = 0; s < 8; s++) {
                    const int ncol = (nwarp << 6) + (s << 3) + r;
                    uint32_t bh[2], bl[2];
                    bh[0] = __float_as_uint(Bh[ncol * AK + kk]);
                    bh[1] = __float_as_uint(Bh[ncol * AK + kk + 4]);
                    bl[0] = __float_as_uint(Bl[ncol * AK + kk]);
                    bl[1] = __float_as_uint(Bl[ncol * AK + kk + 4]);
                    mma_tf32(acc[s], ah, bh);
                    mma_tf32(acc[s], ah, bl);
                    mma_tf32(acc[s], al, bh);
                }
            }
        }
        // per-tile argmax update (ascending n => strict > keeps first index)
        const int nb0 = n0 + (nwarp << 6) + (q << 1);
        #pragma unroll
        for (int s = 0; s < 8; s++) {
            const int nb = nb0 + (s << 3);
            float v;
            v = acc[s][0]; if (v > best0) { best0 = v; bi0 = nb;     }
            v = acc[s][1]; if (v > best0) { best0 = v; bi0 = nb + 1; }
            v = acc[s][2]; if (v > best1) { best1 = v; bi1 = nb;     }
            v = acc[s][3]; if (v > best1) { best1 = v; bi1 = nb + 1; }
            acc[s][0] = 0.f; acc[s][1] = 0.f; acc[s][2] = 0.f; acc[s][3] = 0.f;
        }
    }
    // quad reduce (lanes sharing a row differ in bits 0..1)
    #pragma unroll
    for (int off = 1; off <= 2; off <<= 1) {
        float ov = __shfl_xor_sync(0xffffffffu, best0, off);
        int   oi = __shfl_xor_sync(0xffffffffu, bi0, off);
        if (ov > best0 || (ov == best0 && oi < bi0)) { best0 = ov; bi0 = oi; }
        ov = __shfl_xor_sync(0xffffffffu, best1, off);
        oi = __shfl_xor_sync(0xffffffffu, bi1, off);
        if (ov > best1 || (ov == best1 && oi < bi1)) { best1 = ov; bi1 = oi; }
    }
    __syncthreads();   // smem reuse for merge
    float* bufV = smm;               // [64][2]
    int*   bufI = (int*)(smm + 128); // [64][2]
    if (q == 0) {
        int row0 = (mwarp << 4) + r;
        bufV[row0 * 2 + nwarp] = best0;  bufI[row0 * 2 + nwarp] = bi0;
        bufV[(row0 + 8) * 2 + nwarp] = best1;
        bufI[(row0 + 8) * 2 + nwarp] = bi1;
    }
    __syncthreads();
    if (tid < 64) {
        float v0 = bufV[tid * 2], v1 = bufV[tid * 2 + 1];
        int   i0 = bufI[tid * 2], i1 = bufI[tid * 2 + 1];
        int bi = (v1 > v0 || (v1 == v0 && i1 < i0)) ? i1 : i0;
        g_idx[m0 + tid] = bi;
        out[OUT_IDX + m0 + tid] = (float)bi;
    }
}

// ---------------------------------------------------------------------------
// Gather z_q[b,d,t] = codebook[idx[b,t]][d]  (un-normalized codebook)
// ---------------------------------------------------------------------------
__global__ __launch_bounds__(256) void gather_kernel(const float* __restrict__ cb)
{
    __shared__ float Ds[32][260];
    const int m0  = blockIdx.x * 32;
    const int tid = threadIdx.x;
    {
        int t_l = tid >> 3;
        int d0  = (tid & 7) << 5;
        int code = g_idx[m0 + t_l];
        const float* crow = cb + (size_t)code * Dd;
        #pragma unroll
        for (int qq = 0; qq < 8; qq++) {
            float4 v = *(const float4*)(crow + d0 + (qq << 2));
            *(float4*)&Ds[t_l][d0 + (qq << 2)] = v;
        }
    }
    __syncthreads();
    {
        int d  = tid;
        int b  = m0 >> 12;
        int t0 = m0 & (Tt - 1);
        float* wr = g_zq + ((size_t)(b * Dd + d)) * Tt + t0;
        #pragma unroll
        for (int qq = 0; qq < 8; qq++) {
            float4 v;
            v.x = Ds[(qq << 2) + 0][d]; v.y = Ds[(qq << 2) + 1][d];
            v.z = Ds[(qq << 2) + 2][d]; v.w = Ds[(qq << 2) + 3][d];
            *(float4*)(wr + (qq << 2)) = v;
        }
    }
}

// ---------------------------------------------------------------------------
// GEMM-out: out[b,c,t] = sum_d W_out[c,d] * z_q[b,d,t] + out_b[c]
// ---------------------------------------------------------------------------
__global__ __launch_bounds__(256) void gemm_out_kernel(
    const float* __restrict__ out_b, float* __restrict__ out)
{
    const int b  = blockIdx.z;
    const int c0 = blockIdx.y * 64;
    const int t0 = blockIdx.x * 64;
    __shared__ float As[16][64];
    __shared__ float Bs[16][64];

    float acc[4][4] = {};
    const int tid = threadIdx.x;
    const int tx = tid & 15, ty = tid >> 4;
    const float* Zb = g_zq + (size_t)b * Dd * Tt;

    for (int k0 = 0; k0 < Dd; k0 += 16) {
        {
            int c  = tid >> 2;
            int kq = (tid & 3) << 2;
            float4 va = *(const float4*)(g_Wout + (size_t)(c0 + c) * Dd + k0 + kq);
            As[kq + 0][c] = va.x; As[kq + 1][c] = va.y;
            As[kq + 2][c] = va.z; As[kq + 3][c] = va.w;
            int kk = tid >> 4;
            int tq = (tid & 15) << 2;
            float4 vb = *(const float4*)(Zb + (size_t)(k0 + kk) * Tt + t0 + tq);
            *(float4*)&Bs[kk][tq] = vb;
        }
        __syncthreads();
        #pragma unroll
        for (int kk = 0; kk < 16; kk++) {
            float a[4], bb[4];
            #pragma unroll
            for (int i = 0; i < 4; i++) a[i] = As[kk][(ty << 2) + i];
            #pragma unroll
            for (int j = 0; j < 4; j++) bb[j] = Bs[kk][(tx << 2) + j];
            #pragma unroll
            for (int i = 0; i < 4; i++)
                #pragma unroll
                for (int j = 0; j < 4; j++)
                    acc[i][j] = fmaf(a[i], bb[j], acc[i][j]);
        }
        __syncthreads();
    }
    #pragma unroll
    for (int i = 0; i < 4; i++) {
        int c = c0 + (ty << 2) + i;
        float bias = out_b[c];
        float4 v;
        v.x = acc[i][0] + bias; v.y = acc[i][1] + bias;
        v.z = acc[i][2] + bias; v.w = acc[i][3] + bias;
        *(float4*)(out + OUT_OUT + ((size_t)(b * Cc + c)) * Tt + t0 + (tx << 2)) = v;
    }
}

// ---------------------------------------------------------------------------
extern "C" void kernel_launch(void* const* d_in, const int* in_sizes, int n_in,
                              void* d_out, int out_size)
{
    const float* z     = (const float*)d_in[0];
    const float* in_v  = (const float*)d_in[1];
    const float* in_g  = (const float*)d_in[2];
    const float* in_b  = (const float*)d_in[3];
    const float* out_v = (const float*)d_in[4];
    const float* out_g = (const float*)d_in[5];
    const float* out_b = (const float*)d_in[6];
    const float* cb    = (const float*)d_in[7];
    float* out = (float*)d_out;

    cudaFuncSetAttribute(argmax_mma_kernel,
                         cudaFuncAttributeMaxDynamicSharedMemorySize, ARG_SMEM);

    // weight norms + codebook normalize (+tf32 split)
    rownorm_kernel<<<Dd, 256>>>(in_v,  in_g,  0, Cc);
    rownorm_kernel<<<Cc, 256>>>(out_v, out_g, 1, Dd);
    rownorm_kernel<<<Kc, 256>>>(cb,    nullptr, 2, Dd);

    // z_e = W_in @ z + b  (emits z_e and tf32 splits of z_e^T)
    {
        dim3 grid(Tt / 64, Dd / 64, Bn);
        gemm_in_kernel<<<grid, 256>>>(z, in_b, out);
    }

    // indices = argmax_k <z_e, cb_n[k]>  (mma.sync tf32, 3-pass)
    argmax_mma_kernel<<<Mm / 64, 256, ARG_SMEM>>>(out);

    // z_q gather
    gather_kernel<<<Mm / 32, 256>>>(cb);

    // out = W_out @ z_q + b
    {
        dim3 grid(Tt / 64, Cc / 64, Bn);
        gemm_out_kernel<<<grid, 256>>>(out_b, out);
    }
}

// round 7
// speedup vs baseline: 1.9398x; 1.1602x over previous
#include <cuda_runtime.h>
#include <math.h>
#include <stdint.h>

// Problem dims (fixed by the dataset)
#define Bn 4
#define Cc 1024
#define Tt 4096
#define Dd 256
#define Kc 8192
#define Mm (Bn*Tt)   // 16384

// Output layout: (out [B,C,T], indices [B,T] as float, z_e [B,D,T])
#define OUT_OUT 0
#define OUT_IDX (Bn*Cc*Tt)            // 16777216
#define OUT_ZE  (OUT_IDX + Bn*Tt)     // 16793600

#define NEG_INF (-3.402823466e38f)

// Scratch (device globals; no runtime allocation)
__device__ float g_Win[Dd*Cc];                 // 1 MB
__device__ float g_Wout[Cc*Dd];                // 1 MB
__device__ float g_cbn_hi[(size_t)Kc*Dd];      // 8 MB  tf32-hi of normalized codebook
__device__ float g_cbn_lo[(size_t)Kc*Dd];      // 8 MB  tf32-lo
__device__ float g_zeT_hi[(size_t)Mm*Dd];      // 16 MB tf32-hi of z_e^T  [m][d]
__device__ float g_zeT_lo[(size_t)Mm*Dd];      // 16 MB tf32-lo
__device__ float g_zq[(size_t)Bn*Dd*Tt];       // 16 MB ([b][d][t])
__device__ int   g_idx[Mm];

__device__ __forceinline__ float to_tf32(float a) {
    uint32_t u;
    asm("cvt.rna.tf32.f32 %0, %1;" : "=r"(u) : "f"(a));
    return __uint_as_float(u);
}

// Warp-level tf32 MMA: D(16x8) += A(16x8) * B(8x8), fp32 accumulate.
__device__ __forceinline__ void mma_tf32(float c[4], const uint32_t a[4],
                                         const uint32_t b[2]) {
    asm volatile(
        "mma.sync.aligned.m16n8k8.row.col.f32.tf32.tf32.f32 "
        "{%0,%1,%2,%3}, {%4,%5,%6,%7}, {%8,%9}, {%0,%1,%2,%3};"
        : "+f"(c[0]), "+f"(c[1]), "+f"(c[2]), "+f"(c[3])
        : "r"(a[0]), "r"(a[1]), "r"(a[2]), "r"(a[3]),
          "r"(b[0]), "r"(b[1]));
}

__device__ __forceinline__ uint32_t smem_u32(const void* p) {
    uint32_t a;
    asm("{ .reg .u64 t; cvta.to.shared.u64 t, %1; cvt.u32.u64 %0, t; }"
        : "=r"(a) : "l"(p));
    return a;
}
__device__ __forceinline__ void cpa16(uint32_t dst, const void* src) {
    asm volatile("cp.async.ca.shared.global [%0], [%1], 16;"
                 :: "r"(dst), "l"(src) : "memory");
}

// ---------------------------------------------------------------------------
// Row-wise L2 normalize: mode 0 -> g_Win, 1 -> g_Wout, 2 -> cbn tf32 splits
// ---------------------------------------------------------------------------
__global__ __launch_bounds__(256) void rownorm_kernel(
    const float* __restrict__ v, const float* __restrict__ g, int mode, int cols)
{
    int r = blockIdx.x;
    const float* row = v + (size_t)r * cols;
    float s = 0.f;
    for (int c = threadIdx.x; c < cols; c += 256) { float x = row[c]; s += x * x; }
    __shared__ float red[32];
    #pragma unroll
    for (int o = 16; o; o >>= 1) s += __shfl_down_sync(0xffffffffu, s, o);
    int lane = threadIdx.x & 31, w = threadIdx.x >> 5;
    if (lane == 0) red[w] = s;
    __syncthreads();
    if (w == 0) {
        s = (lane < 8) ? red[lane] : 0.f;
        #pragma unroll
        for (int o = 4; o; o >>= 1) s += __shfl_down_sync(0xffffffffu, s, o);
        if (lane == 0) red[0] = s;
    }
    __syncthreads();
    float nrm = sqrtf(red[0]);
    if (mode == 2) {
        float scale = 1.f / fmaxf(nrm, 1e-12f);
        for (int c = threadIdx.x; c < cols; c += 256) {
            float x = row[c] * scale;
            float hi = to_tf32(x);
            g_cbn_hi[(size_t)r * cols + c] = hi;
            g_cbn_lo[(size_t)r * cols + c] = to_tf32(x - hi);
        }
    } else {
        float scale = g[r] / nrm;
        float* orow = ((mode == 0) ? g_Win : g_Wout) + (size_t)r * cols;
        for (int c = threadIdx.x; c < cols; c += 256) orow[c] = row[c] * scale;
    }
}

// ---------------------------------------------------------------------------
// GEMM-in: z_e[b,d,t] = sum_c W_in[d,c] * z[b,c,t] + in_b[d]
// Writes z_e to d_out (OUT_ZE) and tf32 hi/lo splits of z_e^T.
// ---------------------------------------------------------------------------
__global__ __launch_bounds__(256) void gemm_in_kernel(
    const float* __restrict__ z, const float* __restrict__ in_b,
    float* __restrict__ out)
{
    const int b  = blockIdx.z;
    const int d0 = blockIdx.y * 64;
    const int t0 = blockIdx.x * 64;
    __shared__ float As[16][64];
    __shared__ float Bs[16][64];
    __shared__ float Cs[64][65];

    float acc[4][4] = {};
    const int tid = threadIdx.x;
    const int tx = tid & 15, ty = tid >> 4;
    const float* Zb = z + (size_t)b * Cc * Tt;

    for (int k0 = 0; k0 < Cc; k0 += 16) {
        {
            int d  = tid >> 2;
            int kq = (tid & 3) << 2;
            float4 va = *(const float4*)(g_Win + (size_t)(d0 + d) * Cc + k0 + kq);
            As[kq + 0][d] = va.x; As[kq + 1][d] = va.y;
            As[kq + 2][d] = va.z; As[kq + 3][d] = va.w;
            int kk = tid >> 4;
            int tq = (tid & 15) << 2;
            float4 vb = *(const float4*)(Zb + (size_t)(k0 + kk) * Tt + t0 + tq);
            *(float4*)&Bs[kk][tq] = vb;
        }
        __syncthreads();
        #pragma unroll
        for (int kk = 0; kk < 16; kk++) {
            float a[4], bb[4];
            #pragma unroll
            for (int i = 0; i < 4; i++) a[i] = As[kk][(ty << 2) + i];
            #pragma unroll
            for (int j = 0; j < 4; j++) bb[j] = Bs[kk][(tx << 2) + j];
            #pragma unroll
            for (int i = 0; i < 4; i++)
                #pragma unroll
                for (int j = 0; j < 4; j++)
                    acc[i][j] = fmaf(a[i], bb[j], acc[i][j]);
        }
        __syncthreads();
    }
    #pragma unroll
    for (int i = 0; i < 4; i++) {
        int dl = (ty << 2) + i;
        int d  = d0 + dl;
        float bias = in_b[d];
        float4 v;
        v.x = acc[i][0] + bias; v.y = acc[i][1] + bias;
        v.z = acc[i][2] + bias; v.w = acc[i][3] + bias;
        *(float4*)(out + OUT_ZE + ((size_t)(b * Dd + d)) * Tt + t0 + (tx << 2)) = v;
        Cs[(tx << 2) + 0][dl] = v.x; Cs[(tx << 2) + 1][dl] = v.y;
        Cs[(tx << 2) + 2][dl] = v.z; Cs[(tx << 2) + 3][dl] = v.w;
    }
    __syncthreads();
    #pragma unroll
    for (int r = 0; r < 16; r++) {
        int tl = (tid >> 6) + (r << 2);
        int dl = tid & 63;
        float v  = Cs[tl][dl];
        float hi = to_tf32(v);
        size_t o = ((size_t)(b * Tt + t0 + tl)) * Dd + d0 + dl;
        g_zeT_hi[o] = hi;
        g_zeT_lo[o] = to_tf32(v - hi);
    }
}

// ---------------------------------------------------------------------------
// Scoring + argmax via mma.sync tf32 3-pass, cp.async 2-stage pipeline.
// CTA: 128 rows, 256 thr = 8 warps (4 m-warps x 2 n-warps); warp m32 x n64.
// N in 128-wide tiles; K=256 in 32-wide chunks; 512 chunks total, prefetch
// chunk c+1 while computing chunk c. AK=36 padding: conflict-free LDS.
// ---------------------------------------------------------------------------
#define AK        36
#define ARR_FL    (128 * AK)           // 4608 floats per array
#define STAGE_FL  (4 * ARR_FL)         // 18432 floats per stage
#define STAGE_BY  (STAGE_FL * 4)       // 73728 B
#define OFF_AH    0
#define OFF_AL    (ARR_FL * 4)
#define OFF_BH    (2 * ARR_FL * 4)
#define OFF_BL    (3 * ARR_FL * 4)
#define ARG_SMEM  (2 * STAGE_BY)       // 147456 B
#define NCHUNKS   ((Kc / 128) * 8)     // 512

__device__ __forceinline__ void load_chunk(uint32_t sb, int c, int m0) {
    const int n0 = (c >> 3) << 7;
    const int k0 = (c & 7) << 5;
    const uint32_t st = sb + (uint32_t)(c & 1) * STAGE_BY;
    const int t = threadIdx.x;
    #pragma unroll
    for (int p = 0; p < 4; p++) {
        int idx = t + (p << 8);
        int row = idx >> 3;
        int f4  = (idx & 7) << 2;
        uint32_t da = st + (uint32_t)(row * AK + f4) * 4;
        size_t ga = (size_t)(m0 + row) * Dd + k0 + f4;
        cpa16(da + OFF_AH, g_zeT_hi + ga);
        cpa16(da + OFF_AL, g_zeT_lo + ga);
        size_t gb = (size_t)(n0 + row) * Dd + k0 + f4;
        cpa16(da + OFF_BH, g_cbn_hi + gb);
        cpa16(da + OFF_BL, g_cbn_lo + gb);
    }
}

__global__ __launch_bounds__(256, 1) void argmax_mma_kernel(float* __restrict__ out)
{
    extern __shared__ float smm[];
    const uint32_t sb = smem_u32(smm);

    const int tid  = threadIdx.x;
    const int wid  = tid >> 5, lane = tid & 31;
    const int q    = lane & 3, r = lane >> 2;
    const int mwarp = wid >> 1, nwarp = wid & 1;
    const int m0   = blockIdx.x * 128;

    float acc[2][8][4] = {};
    float best[2][2]; int bidx[2][2];
    #pragma unroll
    for (int mt = 0; mt < 2; mt++)
        #pragma unroll
        for (int h = 0; h < 2; h++) { best[mt][h] = NEG_INF; bidx[mt][h] = 0; }

    load_chunk(sb, 0, m0);
    asm volatile("cp.async.commit_group;" ::: "memory");

    #pragma unroll 1
    for (int c = 0; c < NCHUNKS; ++c) {
        if (c + 1 < NCHUNKS) {
            load_chunk(sb, c + 1, m0);
            asm volatile("cp.async.commit_group;" ::: "memory");
            asm volatile("cp.async.wait_group 1;" ::: "memory");
        } else {
            asm volatile("cp.async.wait_group 0;" ::: "memory");
        }
        __syncthreads();

        const float* base = smm + (c & 1) * STAGE_FL;
        const float* Ah = base;
        const float* Al = base + ARR_FL;
        const float* Bh = base + 2 * ARR_FL;
        const float* Bl = base + 3 * ARR_FL;

        #pragma unroll
        for (int k8 = 0; k8 < 4; k8++) {
            const int kk = (k8 << 3) + q;
            uint32_t ah[2][4], al[2][4];
            #pragma unroll
            for (int mt = 0; mt < 2; mt++) {
                const int ar = (mwarp << 5) + (mt << 4) + r;
                ah[mt][0] = __float_as_uint(Ah[ar * AK + kk]);
                ah[mt][1] = __float_as_uint(Ah[(ar + 8) * AK + kk]);
                ah[mt][2] = __float_as_uint(Ah[ar * AK + kk + 4]);
                ah[mt][3] = __float_as_uint(Ah[(ar + 8) * AK + kk + 4]);
                al[mt][0] = __float_as_uint(Al[ar * AK + kk]);
                al[mt][1] = __float_as_uint(Al[(ar + 8) * AK + kk]);
                al[mt][2] = __float_as_uint(Al[ar * AK + kk + 4]);
                al[mt][3] = __float_as_uint(Al[(ar + 8) * AK + kk + 4]);
            }
            #pragma unroll
            for (int s = 0; s < 8; s++) {
                const int ncol = (nwarp << 6) + (s << 3) + r;
                uint32_t bh[2], bl[2];
                bh[0] = __float_as_uint(Bh[ncol * AK + kk]);
                bh[1] = __float_as_uint(Bh[ncol * AK + kk + 4]);
                bl[0] = __float_as_uint(Bl[ncol * AK + kk]);
                bl[1] = __float_as_uint(Bl[ncol * AK + kk + 4]);
                #pragma unroll
                for (int mt = 0; mt < 2; mt++) {
                    mma_tf32(acc[mt][s], ah[mt], bh);
                    mma_tf32(acc[mt][s], ah[mt], bl);
                    mma_tf32(acc[mt][s], al[mt], bh);
                }
            }
        }

        if ((c & 7) == 7) {
            // finished a full K pass for n-tile (c>>3): argmax update + reset
            const int nb0 = ((c >> 3) << 7) + (nwarp << 6) + (q << 1);
            #pragma unroll
            for (int mt = 0; mt < 2; mt++)
                #pragma unroll
                for (int s = 0; s < 8; s++) {
                    const int nb = nb0 + (s << 3);
                    float v;
                    v = acc[mt][s][0];
                    if (v > best[mt][0]) { best[mt][0] = v; bidx[mt][0] = nb; }
                    v = acc[mt][s][1];
                    if (v > best[mt][0]) { best[mt][0] = v; bidx[mt][0] = nb + 1; }
                    v = acc[mt][s][2];
                    if (v > best[mt][1]) { best[mt][1] = v; bidx[mt][1] = nb; }
                    v = acc[mt][s][3];
                    if (v > best[mt][1]) { best[mt][1] = v; bidx[mt][1] = nb + 1; }
                    acc[mt][s][0] = 0.f; acc[mt][s][1] = 0.f;
                    acc[mt][s][2] = 0.f; acc[mt][s][3] = 0.f;
                }
        }
        __syncthreads();
    }

    // quad reduce (lanes sharing a row differ in bits 0..1), min-index ties
    #pragma unroll
    for (int mt = 0; mt < 2; mt++)
        #pragma unroll
        for (int h = 0; h < 2; h++) {
            #pragma unroll
            for (int off = 1; off <= 2; off <<= 1) {
                float ov = __shfl_xor_sync(0xffffffffu, best[mt][h], off);
                int   oi = __shfl_xor_sync(0xffffffffu, bidx[mt][h], off);
                if (ov > best[mt][h] || (ov == best[mt][h] && oi < bidx[mt][h])) {
                    best[mt][h] = ov; bidx[mt][h] = oi;
                }
            }
        }
    __syncthreads();   // smem reuse for cross-n-warp merge
    float* bufV = smm;               // [128][2]
    int*   bufI = (int*)(smm + 256); // [128][2]
    if (q == 0) {
        #pragma unroll
        for (int mt = 0; mt < 2; mt++)
            #pragma unroll
            for (int h = 0; h < 2; h++) {
                int row = (mwarp << 5) + (mt << 4) + (h << 3) + r;
                bufV[row * 2 + nwarp] = best[mt][h];
                bufI[row * 2 + nwarp] = bidx[mt][h];
            }
    }
    __syncthreads();
    if (tid < 128) {
        float v0 = bufV[tid * 2], v1 = bufV[tid * 2 + 1];
        int   i0 = bufI[tid * 2], i1 = bufI[tid * 2 + 1];
        int bi = (v1 > v0 || (v1 == v0 && i1 < i0)) ? i1 : i0;
        g_idx[m0 + tid] = bi;
        out[OUT_IDX + m0 + tid] = (float)bi;
    }
}

// ---------------------------------------------------------------------------
// Gather z_q[b,d,t] = codebook[idx[b,t]][d]  (un-normalized codebook)
// ---------------------------------------------------------------------------
__global__ __launch_bounds__(256) void gather_kernel(const float* __restrict__ cb)
{
    __shared__ float Ds[32][260];
    const int m0  = blockIdx.x * 32;
    const int tid = threadIdx.x;
    {
        int t_l = tid >> 3;
        int d0  = (tid & 7) << 5;
        int code = g_idx[m0 + t_l];
        const float* crow = cb + (size_t)code * Dd;
        #pragma unroll
        for (int qq = 0; qq < 8; qq++) {
            float4 v = *(const float4*)(crow + d0 + (qq << 2));
            *(float4*)&Ds[t_l][d0 + (qq << 2)] = v;
        }
    }
    __syncthreads();
    {
        int d  = tid;
        int b  = m0 >> 12;
        int t0 = m0 & (Tt - 1);
        float* wr = g_zq + ((size_t)(b * Dd + d)) * Tt + t0;
        #pragma unroll
        for (int qq = 0; qq < 8; qq++) {
            float4 v;
            v.x = Ds[(qq << 2) + 0][d]; v.y = Ds[(qq << 2) + 1][d];
            v.z = Ds[(qq << 2) + 2][d]; v.w = Ds[(qq << 2) + 3][d];
            *(float4*)(wr + (qq << 2)) = v;
        }
    }
}

// ---------------------------------------------------------------------------
// GEMM-out: out[b,c,t] = sum_d W_out[c,d] * z_q[b,d,t] + out_b[c]
// ---------------------------------------------------------------------------
__global__ __launch_bounds__(256) void gemm_out_kernel(
    const float* __restrict__ out_b, float* __restrict__ out)
{
    const int b  = blockIdx.z;
    const int c0 = blockIdx.y * 64;
    const int t0 = blockIdx.x * 64;
    __shared__ float As[16][64];
    __shared__ float Bs[16][64];

    float acc[4][4] = {};
    const int tid = threadIdx.x;
    const int tx = tid & 15, ty = tid >> 4;
    const float* Zb = g_zq + (size_t)b * Dd * Tt;

    for (int k0 = 0; k0 < Dd; k0 += 16) {
        {
            int c  = tid >> 2;
            int kq = (tid & 3) << 2;
            float4 va = *(const float4*)(g_Wout + (size_t)(c0 + c) * Dd + k0 + kq);
            As[kq + 0][c] = va.x; As[kq + 1][c] = va.y;
            As[kq + 2][c] = va.z; As[kq + 3][c] = va.w;
            int kk = tid >> 4;
            int tq = (tid & 15) << 2;
            float4 vb = *(const float4*)(Zb + (size_t)(k0 + kk) * Tt + t0 + tq);
            *(float4*)&Bs[kk][tq] = vb;
        }
        __syncthreads();
        #pragma unroll
        for (int kk = 0; kk < 16; kk++) {
            float a[4], bb[4];
            #pragma unroll
            for (int i = 0; i < 4; i++) a[i] = As[kk][(ty << 2) + i];
            #pragma unroll
            for (int j = 0; j < 4; j++) bb[j] = Bs[kk][(tx << 2) + j];
            #pragma unroll
            for (int i = 0; i < 4; i++)
                #pragma unroll
                for (int j = 0; j < 4; j++)
                    acc[i][j] = fmaf(a[i], bb[j], acc[i][j]);
        }
        __syncthreads();
    }
    #pragma unroll
    for (int i = 0; i < 4; i++) {
        int c = c0 + (ty << 2) + i;
        float bias = out_b[c];
        float4 v;
        v.x = acc[i][0] + bias; v.y = acc[i][1] + bias;
        v.z = acc[i][2] + bias; v.w = acc[i][3] + bias;
        *(float4*)(out + OUT_OUT + ((size_t)(b * Cc + c)) * Tt + t0 + (tx << 2)) = v;
    }
}

// ---------------------------------------------------------------------------
extern "C" void kernel_launch(void* const* d_in, const int* in_sizes, int n_in,
                              void* d_out, int out_size)
{
    const float* z     = (const float*)d_in[0];
    const float* in_v  = (const float*)d_in[1];
    const float* in_g  = (const float*)d_in[2];
    const float* in_b  = (const float*)d_in[3];
    const float* out_v = (const float*)d_in[4];
    const float* out_g = (const float*)d_in[5];
    const float* out_b = (const float*)d_in[6];
    const float* cb    = (const float*)d_in[7];
    float* out = (float*)d_out;

    cudaFuncSetAttribute(argmax_mma_kernel,
                         cudaFuncAttributeMaxDynamicSharedMemorySize, ARG_SMEM);

    // weight norms + codebook normalize (+tf32 split)
    rownorm_kernel<<<Dd, 256>>>(in_v,  in_g,  0, Cc);
    rownorm_kernel<<<Cc, 256>>>(out_v, out_g, 1, Dd);
    rownorm_kernel<<<Kc, 256>>>(cb,    nullptr, 2, Dd);

    // z_e = W_in @ z + b  (emits z_e and tf32 splits of z_e^T)
    {
        dim3 grid(Tt / 64, Dd / 64, Bn);
        gemm_in_kernel<<<grid, 256>>>(z, in_b, out);
    }

    // indices = argmax_k <z_e, cb_n[k]>  (mma.sync tf32, 3-pass, pipelined)
    argmax_mma_kernel<<<Mm / 128, 256, ARG_SMEM>>>(out);

    // z_q gather
    gather_kernel<<<Mm / 32, 256>>>(cb);

    // out = W_out @ z_q + b
    {
        dim3 grid(Tt / 64, Cc / 64, Bn);
        gemm_out_kernel<<<grid, 256>>>(out_b, out);
    }
}